// round 11
// baseline (speedup 1.0000x reference)
#include <cuda_runtime.h>
#include <cuda_fp16.h>
#include <cstdint>
#include <math.h>

#define Bsz 8192
#define Hdim 1024
#define G4 4096
#define HG (1024 * 4096)

#define BM 128      // batch rows per CTA
#define BN 128      // permuted z-cols per CTA (= 32 units x 4 gates)
#define NT 64       // k16 steps
#define NTH 256

// ---------------- device scratch (allocation-free) ----------------
// g_W: B in MMA fragment layout: uint4 unit per [l][kc(64)][pn(256)][lane(32)]
//   unit = { b0(j0), b1(j0), b0(j1), b1(j1) } per PTX m16n8k16 B mapping
__device__ __align__(256) __half g_W[4ull * HG];
// h buffers in A-FRAGMENT layout: uint4 unit per [mblk(512)][kblk(64)][lane(32)]
//   unit = { a0, a1, a2, a3 }: a0=(r,k0|k0+1) a1=(r+8,..) a2=(r,k0+8|9) a3=(r+8,..)
__device__ __align__(256) __half g_h0f[Bsz * Hdim];
__device__ __align__(256) __half g_hfa[Bsz * Hdim];
__device__ __align__(256) __half g_hfb[Bsz * Hdim];
__device__ float  g_ca[Bsz * Hdim];
__device__ float  g_cb[Bsz * Hdim];
__device__ float  g_biasp[4 * G4];       // permuted biases per layer
__device__ float  g_wx0p[G4];            // permuted Wx0

// permuted column layout: n' = (u>>2)*16 + (gate>>1)*8 + (u&3)*2 + (gate&1)
__device__ __forceinline__ int np_to_col(int np) {
    int u = ((np >> 4) << 2) | ((np >> 1) & 3);
    int gate = (((np >> 3) & 1) << 1) | (np & 1);
    return gate * 1024 + u;
}
__device__ __forceinline__ float sigm(float z) { return 1.0f / (1.0f + __expf(-z)); }
__device__ __forceinline__ float tanha(float x) {
    float r; asm("tanh.approx.f32 %0, %1;" : "=f"(r) : "f"(x)); return r;
}
__device__ __forceinline__ uint32_t pack2(__half lo, __half hi) {
    __half2 h = __halves2half2(lo, hi);
    return *(uint32_t*)&h;
}

__device__ __forceinline__ void mma16816(float* d, const uint32_t* a,
                                         uint32_t b0, uint32_t b1) {
    asm volatile(
        "mma.sync.aligned.m16n8k16.row.col.f32.f16.f16.f32 "
        "{%0,%1,%2,%3}, {%4,%5,%6,%7}, {%8,%9}, {%0,%1,%2,%3};\n"
        : "+f"(d[0]), "+f"(d[1]), "+f"(d[2]), "+f"(d[3])
        : "r"(a[0]), "r"(a[1]), "r"(a[2]), "r"(a[3]), "r"(b0), "r"(b1));
}

// ---------------- prep kernels ----------------
// Fold Wx+Wh, permute n', emit B fragment layout (verified in R10).
__global__ void wprep_kernel(const float* __restrict__ Wh0,
                             const float* __restrict__ Wx,
                             const float* __restrict__ Wh) {
    int b = blockIdx.x;            // [l(4)][kc(64)][png(16)]
    int png = b & 15;
    int kc  = (b >> 4) & 63;
    int l   = b >> 10;
    __shared__ __half sm[16][264];
    int tid = threadIdx.x;

    for (int i = tid; i < 4096; i += 256) {
        int uu = i & 63;
        int gate = (i >> 6) & 3;
        int k = i >> 8;
        int col = gate * 1024 + png * 64 + uu;
        int row = kc * 16 + k;
        float v;
        if (l == 0) {
            v = Wh0[(size_t)row * 4096 + col];
        } else {
            size_t o = (size_t)(l - 1) * HG + (size_t)row * 4096 + col;
            v = Wx[o] + Wh[o];
        }
        int npl = ((uu >> 2) << 4) | ((gate >> 1) << 3) | ((uu & 3) << 1) | (gate & 1);
        sm[k][npl] = __float2half_rn(v);
    }
    __syncthreads();

    for (int i = tid; i < 512; i += 256) {
        int lane = i & 31;
        int pnl = i >> 5;
        int n0 = pnl * 16 + (lane >> 2);
        int kk = (lane & 3) * 2;
        __half h[8];
        h[0] = sm[kk][n0];         h[1] = sm[kk + 1][n0];
        h[2] = sm[kk + 8][n0];     h[3] = sm[kk + 9][n0];
        h[4] = sm[kk][n0 + 8];     h[5] = sm[kk + 1][n0 + 8];
        h[6] = sm[kk + 8][n0 + 8]; h[7] = sm[kk + 9][n0 + 8];
        size_t pn = (size_t)png * 16 + pnl;
        size_t unit = (((size_t)l * 64 + kc) * 256 + pn) * 32 + lane;
        ((uint4*)g_W)[unit] = *(const uint4*)h;
    }
}

// h0 -> A-fragment layout. One block per mblk (16 rows).
__global__ void hprep_kernel(const float4* __restrict__ h0) {
    int mb = blockIdx.x;           // 0..511
    __shared__ __half sm[16][1032];
    int tid = threadIdx.x;
    for (int i = tid; i < 4096; i += 256) {       // 16 rows x 256 float4
        int row = i >> 8, c4 = i & 255;
        float4 v = h0[(size_t)(mb * 16 + row) * 256 + c4];
        sm[row][c4 * 4 + 0] = __float2half_rn(v.x);
        sm[row][c4 * 4 + 1] = __float2half_rn(v.y);
        sm[row][c4 * 4 + 2] = __float2half_rn(v.z);
        sm[row][c4 * 4 + 3] = __float2half_rn(v.w);
    }
    __syncthreads();
    for (int i = tid; i < 2048; i += 256) {       // 64 kblk x 32 lanes
        int lane = i & 31, kb = i >> 5;
        int r = lane >> 2;
        int k0 = kb * 16 + 2 * (lane & 3);
        uint4 u;
        u.x = pack2(sm[r][k0],         sm[r][k0 + 1]);
        u.y = pack2(sm[r + 8][k0],     sm[r + 8][k0 + 1]);
        u.z = pack2(sm[r][k0 + 8],     sm[r][k0 + 9]);
        u.w = pack2(sm[r + 8][k0 + 8], sm[r + 8][k0 + 9]);
        ((uint4*)g_h0f)[((size_t)mb * 64 + kb) * 32 + lane] = u;
    }
}
__global__ void bprep_kernel(const float* __restrict__ b0,
                             const float* __restrict__ bb,
                             const float* __restrict__ Wx0) {
    int idx = blockIdx.x * blockDim.x + threadIdx.x;   // < 5*4096
    int np = idx & 4095;
    int l = idx >> 12;
    int col = np_to_col(np);
    if (l < 4) {
        g_biasp[idx] = (l == 0) ? b0[col] : bb[(l - 1) * G4 + col];
    } else {
        g_wx0p[np] = Wx0[col];
    }
}

// ---- fused LSTM layer: ZERO staging; both operands direct fragment LDG ----
__global__ void __launch_bounds__(NTH, 2)
lstm_layer_kernel(int layer,
                  const float* __restrict__ xvec,
                  const float* __restrict__ c0ext,
                  float* __restrict__ dout)
{
    const __half *Af;
    const float *c_in;
    float *c_out;
    __half *h_out_frag;   // A-frag layout (layers 0-2)
    float *h_out_f;       // fp32 row-major (layer 3)
    if (layer == 0) {
        Af = g_h0f; c_in = c0ext;
        c_out = g_ca; h_out_frag = g_hfa; h_out_f = nullptr;
    } else if (layer == 1) {
        Af = g_hfa; c_in = g_ca;
        c_out = g_cb; h_out_frag = g_hfb; h_out_f = nullptr;
    } else if (layer == 2) {
        Af = g_hfb; c_in = g_cb;
        c_out = g_ca; h_out_frag = g_hfa; h_out_f = nullptr;
    } else {
        Af = g_hfa; c_in = g_ca;
        c_out = dout; h_out_frag = nullptr; h_out_f = dout + (size_t)Bsz * Hdim;
    }
    const bool is_l0 = (layer == 0);
    const float* biasp = g_biasp + layer * G4;

    const int tid  = threadIdx.x;
    const int lane = tid & 31;
    const int wid  = tid >> 5;
    const int wm   = wid >> 2;        // 0..1  (64 m rows each)
    const int wn   = wid & 3;         // 0..3  (32 n' cols each)
    const int rowBase = blockIdx.y * BM;
    const int nBase   = blockIdx.x * BN;

    // A frag pointer: unit = (mblk*64 + t)*32 + lane, mblk = rowBase/16 + wm*4 + mt
    const uint4* Abase = ((const uint4*)Af)
        + ((size_t)(rowBase / 16 + wm * 4) * 64) * 32 + lane;
    // B frag pointer: unit = ((l*64 + t)*256 + pn)*32 + lane, pn = bx*8 + wn*2 + jp
    const uint4* Bbase = ((const uint4*)g_W) + (size_t)layer * 524288
        + ((size_t)(blockIdx.x * 8 + wn * 2)) * 32 + lane;

    float acc[4][4][4];
    #pragma unroll
    for (int mt = 0; mt < 4; mt++)
        #pragma unroll
        for (int j = 0; j < 4; j++)
            #pragma unroll
            for (int r = 0; r < 4; r++) acc[mt][j][r] = 0.0f;

    uint32_t af[4][4];        // A frags, rolling per-mt reload (1 step ahead)
    uint32_t bf[2][4][2];     // B frags, double-buffered over t

    auto loadA = [&](int mt, int t) {
        uint4 v = __ldg(Abase + (size_t)mt * 2048 + t * 32);
        af[mt][0] = v.x; af[mt][1] = v.y; af[mt][2] = v.z; af[mt][3] = v.w;
    };
    auto loadB = [&](int nb, int t) {
        uint4 v0 = __ldg(Bbase + (size_t)t * 8192);
        uint4 v1 = __ldg(Bbase + (size_t)t * 8192 + 32);
        bf[nb][0][0] = v0.x; bf[nb][0][1] = v0.y;
        bf[nb][1][0] = v0.z; bf[nb][1][1] = v0.w;
        bf[nb][2][0] = v1.x; bf[nb][2][1] = v1.y;
        bf[nb][3][0] = v1.z; bf[nb][3][1] = v1.w;
    };

    // one k16-step; prefetch t+1's fragments in the tensor shadow
    auto tstep = [&](int cur, int t) {
        const bool pf = (t < NT - 1);
        if (pf) loadB(cur ^ 1, t + 1);
        #pragma unroll
        for (int j = 0; j < 4; j++)
            mma16816(acc[0][j], af[0], bf[cur][j][0], bf[cur][j][1]);
        if (pf) loadA(0, t + 1);
        #pragma unroll
        for (int j = 0; j < 4; j++)
            mma16816(acc[1][j], af[1], bf[cur][j][0], bf[cur][j][1]);
        if (pf) loadA(1, t + 1);
        #pragma unroll
        for (int j = 0; j < 4; j++)
            mma16816(acc[2][j], af[2], bf[cur][j][0], bf[cur][j][1]);
        if (pf) loadA(2, t + 1);
        #pragma unroll
        for (int j = 0; j < 4; j++)
            mma16816(acc[3][j], af[3], bf[cur][j][0], bf[cur][j][1]);
        if (pf) loadA(3, t + 1);
    };

    // prologue: t=0 fragments
    loadB(0, 0);
    #pragma unroll
    for (int mt = 0; mt < 4; mt++) loadA(mt, 0);

    for (int t = 0; t < NT; t += 2) {
        tstep(0, t);
        tstep(1, t + 1);
    }

    // ---- epilogue: gates + cell update; h repacked to A-frag layout ----
    __shared__ __half hs[128][40];
    const int a4 = lane & 3;
    #pragma unroll
    for (int mt = 0; mt < 4; mt++) {
        #pragma unroll
        for (int rh = 0; rh < 2; rh++) {
            const int rloc = wm * 64 + mt * 16 + (lane >> 2) + rh * 8;
            const int row = rowBase + rloc;
            const float xr = is_l0 ? xvec[row] : 0.0f;
            #pragma unroll
            for (int g16 = 0; g16 < 2; g16++) {
                const int nl = wn * 32 + g16 * 16 + a4 * 2;     // n' of gate0
                const int ul = wn * 8 + g16 * 4 + a4;           // local unit
                const int u  = blockIdx.x * 32 + ul;
                float zi = acc[mt][g16 * 2 + 0][rh * 2 + 0] + biasp[nBase + nl];
                float zf = acc[mt][g16 * 2 + 0][rh * 2 + 1] + biasp[nBase + nl + 1];
                float zg = acc[mt][g16 * 2 + 1][rh * 2 + 0] + biasp[nBase + nl + 8];
                float zo = acc[mt][g16 * 2 + 1][rh * 2 + 1] + biasp[nBase + nl + 9];
                if (is_l0) {
                    zi += xr * g_wx0p[nBase + nl];
                    zf += xr * g_wx0p[nBase + nl + 1];
                    zg += xr * g_wx0p[nBase + nl + 8];
                    zo += xr * g_wx0p[nBase + nl + 9];
                }
                const float ig = sigm(zi);
                const float fg = sigm(zf);
                const float gg = tanha(zg);
                const float og = sigm(zo);
                const size_t off = (size_t)row * Hdim + u;
                const float cn = fg * c_in[off] + ig * gg;
                c_out[off] = cn;
                const float hv = og * tanha(cn);
                if (h_out_f) h_out_f[off] = hv;
                else         hs[rloc][ul] = __float2half_rn(hv);
            }
        }
    }
    if (h_out_frag) {
        __syncthreads();
        // emit 512 A-frag units (8 mblk x 2 kblk x 32 lanes), 2 per thread
        #pragma unroll
        for (int i = tid; i < 512; i += 256) {
            int l2 = i & 31, kbl = (i >> 5) & 1, mbl = i >> 6;
            int r0 = mbl * 16 + (l2 >> 2);
            int k0 = kbl * 16 + 2 * (l2 & 3);
            uint4 u;
            u.x = pack2(hs[r0][k0],         hs[r0][k0 + 1]);
            u.y = pack2(hs[r0 + 8][k0],     hs[r0 + 8][k0 + 1]);
            u.z = pack2(hs[r0][k0 + 8],     hs[r0][k0 + 9]);
            u.w = pack2(hs[r0 + 8][k0 + 8], hs[r0 + 8][k0 + 9]);
            size_t unit = ((size_t)(blockIdx.y * 8 + mbl) * 64
                           + (blockIdx.x * 2 + kbl)) * 32 + l2;
            ((uint4*)h_out_frag)[unit] = u;
        }
    }
}

// ---------------- prediction head ----------------
__global__ void head_kernel(const float* __restrict__ h,
                            const float* __restrict__ Wd,
                            const float* __restrict__ bd,
                            float* __restrict__ out)
{
    int warpg = (blockIdx.x * blockDim.x + threadIdx.x) >> 5;
    int lane = threadIdx.x & 31;
    const float4* hp = (const float4*)(h + (size_t)warpg * Hdim);
    const float4* wp = (const float4*)Wd;
    float s = 0.0f;
    #pragma unroll
    for (int i = 0; i < 8; i++) {
        float4 a = hp[lane + i * 32];
        float4 w = wp[lane + i * 32];
        s += a.x * w.x + a.y * w.y + a.z * w.z + a.w * w.w;
    }
    #pragma unroll
    for (int o = 16; o; o >>= 1) s += __shfl_xor_sync(0xffffffffu, s, o);
    if (lane == 0) out[warpg] = s + bd[0];
}

extern "C" void kernel_launch(void* const* d_in, const int* in_sizes, int n_in,
                              void* d_out, int out_size)
{
    const float* x   = (const float*)d_in[0];
    const float* c0  = (const float*)d_in[1];
    const float* h0  = (const float*)d_in[2];
    const float* Wx0 = (const float*)d_in[3];
    const float* Wh0 = (const float*)d_in[4];
    const float* b0  = (const float*)d_in[5];
    const float* Wx  = (const float*)d_in[6];
    const float* Wh  = (const float*)d_in[7];
    const float* bb  = (const float*)d_in[8];
    const float* Wd  = (const float*)d_in[9];
    const float* bd  = (const float*)d_in[10];
    float* out = (float*)d_out;  // [c | h | x_pred]

    wprep_kernel<<<4 * 64 * 16, 256>>>(Wh0, Wx, Wh);
    hprep_kernel<<<Bsz / 16, 256>>>((const float4*)h0);
    bprep_kernel<<<(5 * G4) / 256, 256>>>(b0, bb, Wx0);

    dim3 grid(G4 / BN, Bsz / BM);   // 32 x 64 = 2048 CTAs
    for (int l = 0; l < 4; l++)
        lstm_layer_kernel<<<grid, NTH>>>(l, x, c0, out);

    head_kernel<<<Bsz / 8, 256>>>(out + (size_t)Bsz * Hdim, Wd, bd,
                                  out + 2ull * (size_t)Bsz * Hdim);
}